// round 2
// baseline (speedup 1.0000x reference)
#include <cuda_runtime.h>

// Problem dims (fixed by the reference)
#define B_DIM 256
#define N_DIM 4096
#define KC    128           // C*M = 8*16 reduction length
#define SPLIT 4             // blocks per batch row
#define TPB   256           // threads per block (each owns 4 n via float4)

__device__ float g_pval[B_DIM * SPLIT];
__device__ int   g_pidx[B_DIM * SPLIT];

__global__ __launch_bounds__(TPB, 8)
void conv_argmax_kernel(const float* __restrict__ x,
                        const float* __restrict__ W,
                        float* __restrict__ out) {
    const int blk = blockIdx.x;
    const int b   = blk >> 2;       // /SPLIT
    const int s   = blk & 3;        // %SPLIT
    const int t   = threadIdx.x;

    __shared__ float w[KC];
    if (t < KC) w[t] = W[t];
    __syncthreads();

    const int n0 = s * (TPB * 4) + t * 4;
    const float4* xp = reinterpret_cast<const float4*>(
        x + (size_t)b * (KC * (size_t)N_DIM) + n0);

    float ax = 0.f, ay = 0.f, az = 0.f, aw = 0.f;
#pragma unroll 8
    for (int k = 0; k < KC; k++) {
        float4 v = __ldg(&xp[k * (N_DIM / 4)]);
        float wk = w[k];
        ax = fmaf(v.x, wk, ax);
        ay = fmaf(v.y, wk, ay);
        az = fmaf(v.z, wk, az);
        aw = fmaf(v.w, wk, aw);
    }

    // write outputs[b][n0..n0+3]
    reinterpret_cast<float4*>(out + (size_t)b * N_DIM + n0)[0] =
        make_float4(ax, ay, az, aw);

    // thread-local argmax (ascending scan -> first-occurrence tie-break)
    float bv = ax; int bi = n0;
    if (ay > bv) { bv = ay; bi = n0 + 1; }
    if (az > bv) { bv = az; bi = n0 + 2; }
    if (aw > bv) { bv = aw; bi = n0 + 3; }

    // warp reduce (value, index), tie -> lower index
#pragma unroll
    for (int off = 16; off; off >>= 1) {
        float ov = __shfl_down_sync(0xffffffffu, bv, off);
        int   oi = __shfl_down_sync(0xffffffffu, bi, off);
        if (ov > bv || (ov == bv && oi < bi)) { bv = ov; bi = oi; }
    }

    __shared__ float sv[TPB / 32];
    __shared__ int   si[TPB / 32];
    const int warp = t >> 5, lane = t & 31;
    if (lane == 0) { sv[warp] = bv; si[warp] = bi; }
    __syncthreads();

    if (t == 0) {
        bv = sv[0]; bi = si[0];
#pragma unroll
        for (int i = 1; i < TPB / 32; i++) {
            if (sv[i] > bv || (sv[i] == bv && si[i] < bi)) { bv = sv[i]; bi = si[i]; }
        }
        g_pval[blk] = bv;
        g_pidx[blk] = bi;
    }
}

__global__ void finalize_kernel(const float* __restrict__ r_target,
                                const float* __restrict__ d_target,
                                float* __restrict__ out) {
    const int b = threadIdx.x;
    if (b >= B_DIM) return;

    // reduce the SPLIT partials; partials s=0..3 cover ascending n ranges,
    // so strict '>' preserves the first-occurrence (lowest index) semantics.
    float bv = g_pval[b * SPLIT];
    int   bi = g_pidx[b * SPLIT];
#pragma unroll
    for (int s = 1; s < SPLIT; s++) {
        float v = g_pval[b * SPLIT + s];
        int   i = g_pidx[b * SPLIT + s];
        if (v > bv) { bv = v; bi = i; }
    }

    // r_index = idx // 64 ; d_index = idx - (idx // 64) * 64 = idx % 64
    const int r_index = bi >> 6;
    const int d_index = bi & 63;
    // astype(int) truncates toward zero, then the value is compared as float
    const float rv = (float)(int)r_target[r_index];
    const float dv = (float)(int)d_target[d_index];

    const size_t base = (size_t)B_DIM * N_DIM;   // after outputs
    out[base +            b] = dv;               // d
    out[base + B_DIM +    b] = rv;               // r  (inside tuple)
    out[base + 2 * B_DIM + b] = dv;              // d  (inside tuple)
}

extern "C" void kernel_launch(void* const* d_in, const int* in_sizes, int n_in,
                              void* d_out, int out_size) {
    const float* x        = (const float*)d_in[0];  // [256,8,16,4096]
    const float* W        = (const float*)d_in[1];  // [1,8,16,1] -> 128 floats
    const float* r_target = (const float*)d_in[2];  // [64]
    const float* d_target = (const float*)d_in[3];  // [64]
    float* out = (float*)d_out;

    conv_argmax_kernel<<<B_DIM * SPLIT, TPB>>>(x, W, out);
    finalize_kernel<<<1, TPB>>>(r_target, d_target, out);
}